// round 11
// baseline (speedup 1.0000x reference)
#include <cuda_runtime.h>
#include <cuda_bf16.h>
#include <math.h>

// Problem constants
#define NB   128
#define NS   2048
#define NM   50
#define NDK  64
#define NDV  128
#define NK   5
#define NDS  50
#define NQ   1001
#define NPOS (NB*NS)   // 262144

typedef unsigned long long ull;

// ---- packed f32x2 helpers (bit-identical per lane to scalar fp32) ----
__device__ __forceinline__ ull ffma2(ull a, ull b, ull c) {
    ull d;
    asm("fma.rn.f32x2 %0, %1, %2, %3;" : "=l"(d) : "l"(a), "l"(b), "l"(c));
    return d;
}
__device__ __forceinline__ ull fadd2(ull a, ull b) {
    ull d;
    asm("add.rn.f32x2 %0, %1, %2;" : "=l"(d) : "l"(a), "l"(b));
    return d;
}
__device__ __forceinline__ ull pack2(float lo, float hi) {
    ull r; asm("mov.b64 %0, {%1,%2};" : "=l"(r) : "f"(lo), "f"(hi)); return r;
}
__device__ __forceinline__ float2 unpack2(ull v) {
    float2 f; asm("mov.b64 {%0,%1}, %2;" : "=f"(f.x), "=f"(f.y) : "l"(v)); return f;
}

// ---- cp.async helpers ----
__device__ __forceinline__ void cp_async16(void* dst, const void* src) {
    unsigned s = (unsigned)__cvta_generic_to_shared(dst);
    asm volatile("cp.async.ca.shared.global [%0], [%1], 16;" :: "r"(s), "l"(src));
}
__device__ __forceinline__ void cp_commit() {
    asm volatile("cp.async.commit_group;");
}
__device__ __forceinline__ void cp_wait3() {
    asm volatile("cp.async.wait_group 3;");
}

// -------- scratch (__device__ globals; no runtime allocation) --------
__device__ float  g_attn [NQ * 64];            // softmax(q_e @ key_mem^T); [50,64) ZERO
__device__ float  g_sumq [NQ * 64];            // q_e @ summary_w[128:192], stride 64
__device__ float  g_alpha[NQ];
__device__ float  g_beta [NQ * 4];
__device__ float2 g_ea   [NQ * NK * NDV];      // (.x=erase sigmoid, .y=add tanh)
__device__ float  g_reads[(long)NB * NS * NDV];// 134 MB

// ======================= Phase A1: per-question tables =======================
__global__ void build_q_tables(const float* __restrict__ qe_w,
                               const float* __restrict__ key_mem,
                               const float* __restrict__ sum_w,
                               const float* __restrict__ alpha_w,
                               const float* __restrict__ alpha_b,
                               const float* __restrict__ beta_w,
                               const float* __restrict__ beta_b) {
    int q = blockIdx.x;
    int tid = threadIdx.x;           // 64 threads
    __shared__ float qe[64];
    __shared__ float lg[NM];
    qe[tid] = qe_w[q * 64 + tid];
    __syncthreads();

    if (tid < NM) {
        float a = 0.f, s = 0.f;
        #pragma unroll
        for (int k = 0; k < 64; k++) {
            float qk = qe[k];
            a = fmaf(qk, key_mem[tid * 64 + k], a);
            s = fmaf(qk, sum_w[(128 + k) * NDS + tid], s);
        }
        lg[tid] = a;
        g_sumq[q * 64 + tid] = s;
    }
    __syncthreads();

    if (tid < NM) {
        float mx = -1e30f;
        for (int m = 0; m < NM; m++) mx = fmaxf(mx, lg[m]);
        float den = 0.f;
        for (int m = 0; m < NM; m++) den += expf(lg[m] - mx);
        g_attn[q * 64 + tid] = expf(lg[tid] - mx) / den;
    } else {
        g_attn[q * 64 + tid] = 0.f;   // pad m in [50,64): weight 0 => inert
    }

    if (tid == 0) {
        float x = alpha_b[0];
        #pragma unroll
        for (int k = 0; k < 64; k++) x = fmaf(qe[k], alpha_w[k], x);
        g_alpha[q] = fmaxf(x, 0.f) + log1pf(expf(-fabsf(x)));
    }
    if (tid >= 1 && tid < 5) {
        int t = tid - 1;
        float x = beta_b[t];
        #pragma unroll
        for (int k = 0; k < 64; k++) x = fmaf(qe[k], beta_w[k * 4 + t], x);
        g_beta[q * 4 + t] = x;
    }
}

// ================= Phase A2: per-(question,response) erase/add =================
__global__ __launch_bounds__(128)
void build_qr_tables(const float* __restrict__ item_w,
                     const float* __restrict__ vp_w,
                     const float* __restrict__ vp_b,
                     const float* __restrict__ er_w,
                     const float* __restrict__ er_b,
                     const float* __restrict__ ad_w,
                     const float* __restrict__ ad_b) {
    int q = blockIdx.x;
    int v = threadIdx.x;             // 128 threads
    __shared__ float iv[64];
    __shared__ float veS[NK][NDV];

    if (v < 64) iv[v] = item_w[q * 64 + v];
    __syncthreads();

    float common = vp_b[v];
    #pragma unroll
    for (int i = 0; i < 64; i++) common = fmaf(iv[i], vp_w[i * NDV + v], common);
    #pragma unroll
    for (int r = 0; r < NK; r++) {
        float x = common;
        #pragma unroll
        for (int k = 0; k < NK; k++) {
            float rf = fmaxf(0.f, 1.f - fabsf((float)k - (float)r) * 0.25f);
            x = fmaf(rf, vp_w[(64 + k) * NDV + v], x);
        }
        veS[r][v] = x;
    }
    __syncthreads();

    int j = v;
    float eacc[NK], aacc[NK];
    #pragma unroll
    for (int r = 0; r < NK; r++) { eacc[r] = er_b[j]; aacc[r] = ad_b[j]; }
    for (int v2 = 0; v2 < NDV; v2++) {
        float we = er_w[v2 * NDV + j];
        float wa = ad_w[v2 * NDV + j];
        #pragma unroll
        for (int r = 0; r < NK; r++) {
            float t = veS[r][v2];
            eacc[r] = fmaf(t, we, eacc[r]);
            aacc[r] = fmaf(t, wa, aacc[r]);
        }
    }
    #pragma unroll
    for (int r = 0; r < NK; r++) {
        long base = ((long)q * NK + r) * NDV + j;
        g_ea[base] = make_float2(1.f / (1.f + expf(-eacc[r])), tanhf(aacc[r]));
    }
}

// ========================= Phase B: sequential scan =========================
// One CTA of 256 threads (8 warps) per batch element. Each WARP is autonomous:
// it owns d in [16w, 16w+16), part = lane&1 splits m into 13 packed pairs, and
// it stages its OWN ea (128B) + attn (208B) per step via one 21-lane
// cp.async.16 into a private smem ring (RD slots x SLOT steps). The loop has
// NO CTA barriers: per-warp cp.async.wait_group + __syncwarp only.
#define SLOT 4        // steps per ring slot / cp.async group
#define RD   6        // ring slots; > prefetch depth 4
__global__ __launch_bounds__(256, 1)
void scan_kernel(const int* __restrict__ questions,
                 const int* __restrict__ responses,
                 const float* __restrict__ init_mem) {
    int b = blockIdx.x;
    int tid = threadIdx.x;
    int w    = tid >> 5;
    int lane = tid & 31;
    int part = lane & 1;
    int d = 16 * w + (lane >> 1);    // 0..127
    __shared__ int    qsh[NS + 16];  // q | (r<<16), padded with dup of last
    __shared__ float2 ea_ring[8][RD][SLOT][16];
    __shared__ float  attn_ring[8][RD][SLOT][56];

    for (int i = tid; i < NS; i += 256)
        qsh[i] = questions[b * NS + i] | (responses[b * NS + i] << 16);
    if (tid < 16)
        qsh[NS + tid] = questions[b * NS + NS - 1] | (responses[b * NS + NS - 1] << 16);

    // init mem: part p owns pairs [13p, 13p+13); pair pi covers m = 2pi, 2pi+1
    ull mem2[13];
    #pragma unroll
    for (int jj = 0; jj < 13; jj++) {
        int pi = 13 * part + jj;
        float lo = (2 * pi < NM)     ? init_mem[(2 * pi) * NDV + d]     : 0.f;
        float hi = (2 * pi + 1 < NM) ? init_mem[(2 * pi + 1) * NDV + d] : 0.f;
        mem2[jj] = pack2(lo, hi);
    }
    __syncthreads();                 // qsh ready; the ONLY CTA barrier

    // per-warp cp duty: lanes 0..7 -> ea 16B chunk (2 d-columns);
    //                   lanes 8..20 -> attn 16B chunk
    int eaoff   = 16 * w + lane * 2;           // lanes 0..7
    int attnoff = (lane - 8) * 4;              // lanes 8..20

    float* outp = g_reads + ((long)b * NS) * NDV + d;

    // prologue: issue slots 0..3 (steps 0..15)
    #pragma unroll
    for (int p = 0; p < 4; p++) {
        #pragma unroll
        for (int k = 0; k < SLOT; k++) {
            int v = qsh[SLOT * p + k];
            int qq = v & 0xffff, rr = v >> 16;
            if (lane < 8)
                cp_async16(&ea_ring[w][p][k][lane * 2],
                           &g_ea[(qq * NK + rr) * NDV + eaoff]);
            else if (lane < 21)
                cp_async16(&attn_ring[w][p][k][attnoff],
                           g_attn + qq * 64 + attnoff);
        }
        cp_commit();
    }

    for (int p = 0; p < NS / SLOT; p++) {
        cp_wait3();                  // this warp's slot p complete
        __syncwarp();                // order smem reads after async writes
        int slot = p % RD;

        #pragma unroll
        for (int k = 0; k < SLOT; k++) {
            int t = SLOT * p + k;
            float2 ea = ea_ring[w][slot][k][lane >> 1];
            ull ne2 = pack2(-ea.x, -ea.x);
            ull a2  = pack2(ea.y, ea.y);
            const float2* at = (const float2*)attn_ring[w][slot][k] + 13 * part;

            ull r0 = 0ULL, r1 = 0ULL;
            #pragma unroll
            for (int jj = 0; jj < 13; jj++) {
                float2 wf = at[jj];
                ull w2 = pack2(wf.x, wf.y);
                ull mo = mem2[jj];
                if (jj & 1) r1 = ffma2(w2, mo, r1);
                else        r0 = ffma2(w2, mo, r0);
                mem2[jj] = ffma2(w2, ffma2(mo, ne2, a2), mo);
            }
            float2 rr = unpack2(fadd2(r0, r1));
            float rsum = rr.x + rr.y;
            rsum += __shfl_xor_sync(0xffffffffu, rsum, 1);
            if (part == 0) outp[(long)t * NDV] = rsum;
        }

        // issue slot p+4 into ring slot (p+4)%RD (this warp last read it at p-2)
        int pn = p + 4;
        int slotn = pn % RD;
        #pragma unroll
        for (int k = 0; k < SLOT; k++) {
            int idx = SLOT * pn + k;
            if (idx > NS + 15) idx = NS + 15;
            int v = qsh[idx];
            int qq = v & 0xffff, rr2 = v >> 16;
            if (lane < 8)
                cp_async16(&ea_ring[w][slotn][k][lane * 2],
                           &g_ea[(qq * NK + rr2) * NDV + eaoff]);
            else if (lane < 21)
                cp_async16(&attn_ring[w][slotn][k][attnoff],
                           g_attn + qq * 64 + attnoff);
        }
        cp_commit();                 // keep per-warp group count in sync
    }
}

// ===================== Phase C: summary / outputs =====================
// CT=32 positions/block, 128 threads; 8 pos-groups x 13 j-groups = 104 active.
// rS row stride 132 (pg conflict-free); wS row stride 56 so the 13 jg-group
// 16B loads land on banks jg*4 mod 32 => max 2-way conflict (was 7-way at 52).
#define CT 32
#define WSTR 56
__global__ __launch_bounds__(128)
void output_kernel(const int* __restrict__ questions,
                   const float* __restrict__ sum_w,    // (192,50); rows 0..127 used
                   const float* __restrict__ sum_b,
                   const float* __restrict__ theta_w,
                   const float* __restrict__ theta_b,
                   float* __restrict__ out) {
    __shared__ float rS[CT][132];    // reads tile; later reused as summary (CT x 52)
    __shared__ float wS[128 * WSTR];
    __shared__ float twS[52];

    int tid = threadIdx.x;
    long p0 = (long)blockIdx.x * CT;

    for (int i = tid; i < 128 * WSTR; i += 128) {
        int dd = i / WSTR, j = i % WSTR;
        wS[i] = (j < NDS) ? sum_w[dd * NDS + j] : 0.f;
    }
    if (tid < 52) twS[tid] = (tid < NDS) ? theta_w[tid] : 0.f;
    for (int i = tid; i < CT * 128; i += 128) {
        int pos = i >> 7, dd = i & 127;
        rS[pos][dd] = g_reads[p0 * 128 + i];
    }
    __syncthreads();

    int pg = tid / 13;
    int jg = tid - pg * 13;
    bool active = (tid < 104);
    int jbase = jg * 4;
    ull acc[4][2];
    if (active) {
        #pragma unroll
        for (int pp = 0; pp < 4; pp++) { acc[pp][0] = 0ULL; acc[pp][1] = 0ULL; }
        for (int dd0 = 0; dd0 < 128; dd0 += 4) {
            ulonglong2 wv[4];
            #pragma unroll
            for (int u = 0; u < 4; u++)
                wv[u] = *(const ulonglong2*)&wS[(dd0 + u) * WSTR + jbase];
            #pragma unroll
            for (int pp = 0; pp < 4; pp++) {
                float4 rv = *(const float4*)&rS[pg + pp * 8][dd0];
                ull r0 = pack2(rv.x, rv.x);
                acc[pp][0] = ffma2(r0, wv[0].x, acc[pp][0]);
                acc[pp][1] = ffma2(r0, wv[0].y, acc[pp][1]);
                ull r1 = pack2(rv.y, rv.y);
                acc[pp][0] = ffma2(r1, wv[1].x, acc[pp][0]);
                acc[pp][1] = ffma2(r1, wv[1].y, acc[pp][1]);
                ull r2 = pack2(rv.z, rv.z);
                acc[pp][0] = ffma2(r2, wv[2].x, acc[pp][0]);
                acc[pp][1] = ffma2(r2, wv[2].y, acc[pp][1]);
                ull r3 = pack2(rv.w, rv.w);
                acc[pp][0] = ffma2(r3, wv[3].x, acc[pp][0]);
                acc[pp][1] = ffma2(r3, wv[3].y, acc[pp][1]);
            }
        }
    }
    __syncthreads();   // all reads of rS done; now reuse as summary tile

    float* sS = (float*)rS;          // CT x 52 summary
    if (active) {
        #pragma unroll
        for (int pp = 0; pp < 4; pp++) {
            int pos = pg + pp * 8;
            long p = p0 + pos;
            int q = questions[p];
            float2 a01 = unpack2(acc[pp][0]);
            float2 a23 = unpack2(acc[pp][1]);
            float av[4] = {a01.x, a01.y, a23.x, a23.y};
            #pragma unroll
            for (int jj = 0; jj < 4; jj++) {
                int j = jbase + jj;
                float s = 0.f;
                if (j < NDS)
                    s = tanhf(av[jj] + g_sumq[q * 64 + j] + sum_b[j]);
                sS[pos * 52 + j] = s;
            }
        }
    }
    __syncthreads();

    if (tid < CT) {
        long p = p0 + tid;
        int q = questions[p];
        float th = theta_b[0];
        #pragma unroll
        for (int j = 0; j < NDS; j++) th = fmaf(sS[tid * 52 + j], twS[j], th);
        th = tanhf(th);
        float al = g_alpha[q];
        float inter = th * al;
        float bt[4];
        #pragma unroll
        for (int t = 0; t < 4; t++) bt[t] = g_beta[q * 4 + t];
        float lg[5];
        lg[0] = 0.f;
        float c = 0.f;
        #pragma unroll
        for (int t = 0; t < 4; t++) { c += inter - bt[t]; lg[t + 1] = c; }
        float mx = lg[0];
        #pragma unroll
        for (int i = 1; i < 5; i++) mx = fmaxf(mx, lg[i]);
        float ex[5], den = 0.f;
        #pragma unroll
        for (int i = 0; i < 5; i++) { ex[i] = expf(lg[i] - mx); den += ex[i]; }
        float inv = 1.f / den;

        const long NBS = (long)NPOS;
        out[p]               = th;           // theta
        out[NBS + p]         = al;           // alpha
        #pragma unroll
        for (int t = 0; t < 4; t++) out[2 * NBS + p * 4 + t] = bt[t];   // beta
        #pragma unroll
        for (int i = 0; i < 5; i++) out[6 * NBS + p * 5 + i] = lg[i];   // logits
        #pragma unroll
        for (int i = 0; i < 5; i++) out[11 * NBS + p * 5 + i] = ex[i] * inv; // probs
    }
}

// ============================== launcher ==============================
extern "C" void kernel_launch(void* const* d_in, const int* in_sizes, int n_in,
                              void* d_out, int out_size) {
    const int*   questions    = (const int*)  d_in[0];
    const int*   responses    = (const int*)  d_in[1];
    const float* q_embed_w    = (const float*)d_in[2];
    const float* item_embed_w = (const float*)d_in[3];
    const float* value_proj_w = (const float*)d_in[4];
    const float* value_proj_b = (const float*)d_in[5];
    const float* key_mem      = (const float*)d_in[6];
    const float* init_mem     = (const float*)d_in[7];
    const float* erase_w      = (const float*)d_in[8];
    const float* erase_b      = (const float*)d_in[9];
    const float* add_w        = (const float*)d_in[10];
    const float* add_b        = (const float*)d_in[11];
    const float* summary_w    = (const float*)d_in[12];
    const float* summary_b    = (const float*)d_in[13];
    const float* theta_w      = (const float*)d_in[14];
    const float* theta_b      = (const float*)d_in[15];
    const float* alpha_w      = (const float*)d_in[16];
    const float* alpha_b      = (const float*)d_in[17];
    const float* beta_w       = (const float*)d_in[18];
    const float* beta_b       = (const float*)d_in[19];
    float* out = (float*)d_out;

    build_q_tables<<<NQ, 64>>>(q_embed_w, key_mem, summary_w,
                               alpha_w, alpha_b, beta_w, beta_b);
    build_qr_tables<<<NQ, 128>>>(item_embed_w, value_proj_w, value_proj_b,
                                 erase_w, erase_b, add_w, add_b);
    scan_kernel<<<NB, 256>>>(questions, responses, init_mem);
    output_kernel<<<NPOS / CT, 128>>>(questions, summary_w, summary_b,
                                      theta_w, theta_b, out);
}

// round 12
// speedup vs baseline: 1.3260x; 1.3260x over previous
#include <cuda_runtime.h>
#include <cuda_bf16.h>
#include <math.h>

// Problem constants
#define NB   128
#define NS   2048
#define NM   50
#define NDK  64
#define NDV  128
#define NK   5
#define NDS  50
#define NQ   1001
#define NPOS (NB*NS)   // 262144

typedef unsigned long long ull;

// ---- packed f32x2 helpers (bit-identical per lane to scalar fp32) ----
__device__ __forceinline__ ull ffma2(ull a, ull b, ull c) {
    ull d;
    asm("fma.rn.f32x2 %0, %1, %2, %3;" : "=l"(d) : "l"(a), "l"(b), "l"(c));
    return d;
}
__device__ __forceinline__ ull fadd2(ull a, ull b) {
    ull d;
    asm("add.rn.f32x2 %0, %1, %2;" : "=l"(d) : "l"(a), "l"(b));
    return d;
}
__device__ __forceinline__ ull pack2(float lo, float hi) {
    ull r; asm("mov.b64 %0, {%1,%2};" : "=l"(r) : "f"(lo), "f"(hi)); return r;
}
__device__ __forceinline__ float2 unpack2(ull v) {
    float2 f; asm("mov.b64 {%0,%1}, %2;" : "=f"(f.x), "=f"(f.y) : "l"(v)); return f;
}

// ---- cp.async helpers ----
__device__ __forceinline__ void cp_async8(void* dst, const void* src) {
    unsigned s = (unsigned)__cvta_generic_to_shared(dst);
    asm volatile("cp.async.ca.shared.global [%0], [%1], 8;" :: "r"(s), "l"(src));
}
__device__ __forceinline__ void cp_async16(void* dst, const void* src) {
    unsigned s = (unsigned)__cvta_generic_to_shared(dst);
    asm volatile("cp.async.ca.shared.global [%0], [%1], 16;" :: "r"(s), "l"(src));
}
__device__ __forceinline__ void cp_commit() {
    asm volatile("cp.async.commit_group;");
}
__device__ __forceinline__ void cp_wait3() {
    asm volatile("cp.async.wait_group 3;");
}
#define BAR_SYNC(id, cnt) asm volatile("bar.sync %0, %1;" :: "r"(id), "r"(cnt) : "memory")

// -------- scratch (__device__ globals; no runtime allocation) --------
__device__ float  g_attn [NQ * 64];            // softmax(q_e @ key_mem^T); [50,64) ZERO
__device__ float  g_sumq [NQ * 64];            // q_e @ summary_w[128:192], stride 64
__device__ float  g_alpha[NQ];
__device__ float  g_beta [NQ * 4];
__device__ float2 g_ea   [NQ * NK * NDV];      // (.x=erase sigmoid, .y=add tanh)

// ======================= Phase A1: per-question tables =======================
__global__ void build_q_tables(const float* __restrict__ qe_w,
                               const float* __restrict__ key_mem,
                               const float* __restrict__ sum_w,
                               const float* __restrict__ alpha_w,
                               const float* __restrict__ alpha_b,
                               const float* __restrict__ beta_w,
                               const float* __restrict__ beta_b) {
    int q = blockIdx.x;
    int tid = threadIdx.x;           // 64 threads
    __shared__ float qe[64];
    __shared__ float lg[NM];
    qe[tid] = qe_w[q * 64 + tid];
    __syncthreads();

    if (tid < NM) {
        float a = 0.f, s = 0.f;
        #pragma unroll
        for (int k = 0; k < 64; k++) {
            float qk = qe[k];
            a = fmaf(qk, key_mem[tid * 64 + k], a);
            s = fmaf(qk, sum_w[(128 + k) * NDS + tid], s);
        }
        lg[tid] = a;
        g_sumq[q * 64 + tid] = s;
    }
    __syncthreads();

    if (tid < NM) {
        float mx = -1e30f;
        for (int m = 0; m < NM; m++) mx = fmaxf(mx, lg[m]);
        float den = 0.f;
        for (int m = 0; m < NM; m++) den += expf(lg[m] - mx);
        g_attn[q * 64 + tid] = expf(lg[tid] - mx) / den;
    } else {
        g_attn[q * 64 + tid] = 0.f;   // pad m in [50,64): weight 0 => inert
    }

    if (tid == 0) {
        float x = alpha_b[0];
        #pragma unroll
        for (int k = 0; k < 64; k++) x = fmaf(qe[k], alpha_w[k], x);
        g_alpha[q] = fmaxf(x, 0.f) + log1pf(expf(-fabsf(x)));
    }
    if (tid >= 1 && tid < 5) {
        int t = tid - 1;
        float x = beta_b[t];
        #pragma unroll
        for (int k = 0; k < 64; k++) x = fmaf(qe[k], beta_w[k * 4 + t], x);
        g_beta[q * 4 + t] = x;
    }
}

// ================= Phase A2: per-(question,response) erase/add =================
__global__ __launch_bounds__(128)
void build_qr_tables(const float* __restrict__ item_w,
                     const float* __restrict__ vp_w,
                     const float* __restrict__ vp_b,
                     const float* __restrict__ er_w,
                     const float* __restrict__ er_b,
                     const float* __restrict__ ad_w,
                     const float* __restrict__ ad_b) {
    int q = blockIdx.x;
    int v = threadIdx.x;             // 128 threads
    __shared__ float iv[64];
    __shared__ float veS[NK][NDV];

    if (v < 64) iv[v] = item_w[q * 64 + v];
    __syncthreads();

    float common = vp_b[v];
    #pragma unroll
    for (int i = 0; i < 64; i++) common = fmaf(iv[i], vp_w[i * NDV + v], common);
    #pragma unroll
    for (int r = 0; r < NK; r++) {
        float x = common;
        #pragma unroll
        for (int k = 0; k < NK; k++) {
            float rf = fmaxf(0.f, 1.f - fabsf((float)k - (float)r) * 0.25f);
            x = fmaf(rf, vp_w[(64 + k) * NDV + v], x);
        }
        veS[r][v] = x;
    }
    __syncthreads();

    int j = v;
    float eacc[NK], aacc[NK];
    #pragma unroll
    for (int r = 0; r < NK; r++) { eacc[r] = er_b[j]; aacc[r] = ad_b[j]; }
    for (int v2 = 0; v2 < NDV; v2++) {
        float we = er_w[v2 * NDV + j];
        float wa = ad_w[v2 * NDV + j];
        #pragma unroll
        for (int r = 0; r < NK; r++) {
            float t = veS[r][v2];
            eacc[r] = fmaf(t, we, eacc[r]);
            aacc[r] = fmaf(t, wa, aacc[r]);
        }
    }
    #pragma unroll
    for (int r = 0; r < NK; r++) {
        long base = ((long)q * NK + r) * NDV + j;
        g_ea[base] = make_float2(1.f / (1.f + expf(-eacc[r])), tanhf(aacc[r]));
    }
}

// ==================== Phase B (fused): scan + outputs ====================
// One CTA of 384 threads per batch element b.
//  Warps 0-7  (tid<256): PRODUCERS — R9 cp.async-ring scan (bar.sync 1,256),
//     writing per-step read vectors into a 2-chunk x 32-step smem staging ring.
//  Warps 8-11 (tid>=256): CONSUMERS — per 32-step chunk: GEMM read@W + tanh
//     summary + theta/alpha/beta/logits/probs epilogue (bar.sync 2,128).
//  Producer->consumer: volatile s_prod counter (chunks produced) + fence.
//  Consumer->producer: volatile s_cons counter (chunks consumed) for ring reuse.
#define SLOT  4        // steps per ring slot / cp.async group
#define RD    6        // ring slots; > prefetch depth 4
#define CH    32       // steps per staging chunk
#define NCH   (NS/CH)  // 64 chunks
#define SROW  132      // staging row stride (floats)

// dynamic smem layout (bytes)
#define OFF_QSH  0                          // (NS+16)*4            = 8256
#define OFF_EA   8256                       // RD*SLOT*128*8        = 24576
#define OFF_AT   32832                      // RD*SLOT*56*4         = 5376
#define OFF_STG  38208                      // 64*132*4             = 33792
#define OFF_WS   72000                      // 128*52*4             = 26624
#define OFF_TW   98624                      // 56*4                 = 224
#define OFF_SB   98848                      // 56*4                 = 224
#define SMEM_TOTAL 99072

__global__ __launch_bounds__(384, 1)
void fused_scan_kernel(const int* __restrict__ questions,
                       const int* __restrict__ responses,
                       const float* __restrict__ init_mem,
                       const float* __restrict__ sum_w,
                       const float* __restrict__ sum_b,
                       const float* __restrict__ theta_w,
                       const float* __restrict__ theta_b,
                       float* __restrict__ out) {
    extern __shared__ char smem[];
    int*    qsh       = (int*)   (smem + OFF_QSH);   // q | (r<<16)
    float2* ea_ring   = (float2*)(smem + OFF_EA);    // [RD][SLOT][128]
    float*  attn_ring = (float*) (smem + OFF_AT);    // [RD][SLOT][56]
    float*  staging   = (float*) (smem + OFF_STG);   // [64][SROW]
    float*  wS        = (float*) (smem + OFF_WS);    // [128][52]
    float*  twS       = (float*) (smem + OFF_TW);
    float*  sbS       = (float*) (smem + OFF_SB);

    __shared__ volatile int s_prod;   // chunks produced
    __shared__ volatile int s_cons;   // chunks consumed

    int b   = blockIdx.x;
    int tid = threadIdx.x;

    if (tid == 0) { s_prod = 0; s_cons = 0; }

    if (tid < 256) {
        // producers load qsh
        for (int i = tid; i < NS; i += 256)
            qsh[i] = questions[b * NS + i] | (responses[b * NS + i] << 16);
        if (tid < 16)
            qsh[NS + tid] = questions[b * NS + NS - 1] | (responses[b * NS + NS - 1] << 16);
    } else {
        // consumers load weight tiles
        int ct = tid - 256;          // 0..127
        for (int i = ct; i < 128 * 52; i += 128) {
            int dd = i / 52, j = i % 52;
            wS[i] = (j < NDS) ? sum_w[dd * NDS + j] : 0.f;
        }
        if (ct < 52) {
            twS[ct] = (ct < NDS) ? theta_w[ct] : 0.f;
            sbS[ct] = (ct < NDS) ? sum_b[ct] : 0.f;
        }
    }

    // ---------------- PRODUCERS ----------------
    if (tid < 256) {
        int part = tid & 1;
        int d = tid >> 1;            // 0..127

        // cp duty assignment (R9): ea by all threads (2 step-halves), attn by tid<52
        int d2 = tid & 127;
        int kk = tid >> 7;           // 0 or 1
        int ka = (tid < 52) ? (tid / 13) : 0;
        int ia = (tid < 52) ? (tid % 13) : 0;

        // init mem: part p owns pairs [13p,13p+13); pair pi covers m=2pi,2pi+1
        ull mem2[13];
        #pragma unroll
        for (int jj = 0; jj < 13; jj++) {
            int pi = 13 * part + jj;
            float lo = (2 * pi < NM)     ? init_mem[(2 * pi) * NDV + d]     : 0.f;
            float hi = (2 * pi + 1 < NM) ? init_mem[(2 * pi + 1) * NDV + d] : 0.f;
            mem2[jj] = pack2(lo, hi);
        }
        __syncthreads();             // qsh + weights ready (all 384)

        // prologue: issue slots 0..3 (steps 0..15)
        #pragma unroll
        for (int p = 0; p < 4; p++) {
            #pragma unroll
            for (int kq = 0; kq < 2; kq++) {
                int k = kk * 2 + kq;
                int v = qsh[SLOT * p + k];
                int qq = v & 0xffff, rr = v >> 16;
                cp_async8(&ea_ring[(p * SLOT + k) * 128 + d2],
                          &g_ea[(qq * NK + rr) * NDV + d2]);
            }
            if (tid < 52) {
                int v = qsh[SLOT * p + ka];
                int qq = v & 0xffff;
                cp_async16(&attn_ring[(p * SLOT + ka) * 56 + ia * 4],
                           g_attn + qq * 64 + ia * 4);
            }
            cp_commit();
        }

        for (int p = 0; p < NS / SLOT; p++) {
            cp_wait3();              // slot p complete
            BAR_SYNC(1, 256);        // ring slot + prior-slot staging visible

            // chunk bookkeeping every CH/SLOT = 8 slots
            if ((p & 7) == 0) {
                int c = p >> 3;
                if (c > 0 && tid == 0) { __threadfence_block(); s_prod = c; }
                if (c >= 2) {
                    while (s_cons < c - 1) __nanosleep(200);
                }
            }

            int slot = p % RD;
            #pragma unroll
            for (int k = 0; k < SLOT; k++) {
                int t = SLOT * p + k;
                float2 ea = ea_ring[(slot * SLOT + k) * 128 + d];
                ull ne2 = pack2(-ea.x, -ea.x);
                ull a2  = pack2(ea.y, ea.y);
                const float2* at =
                    (const float2*)(attn_ring + (slot * SLOT + k) * 56) + 13 * part;

                ull r0 = 0ULL, r1 = 0ULL;
                #pragma unroll
                for (int jj = 0; jj < 13; jj++) {
                    float2 wf = at[jj];
                    ull w2 = pack2(wf.x, wf.y);
                    ull mo = mem2[jj];
                    if (jj & 1) r1 = ffma2(w2, mo, r1);
                    else        r0 = ffma2(w2, mo, r0);
                    mem2[jj] = ffma2(w2, ffma2(mo, ne2, a2), mo);
                }
                float2 rr = unpack2(fadd2(r0, r1));
                float rsum = rr.x + rr.y;
                rsum += __shfl_xor_sync(0xffffffffu, rsum, 1);
                if (part == 0) staging[(t & 63) * SROW + d] = rsum;
            }

            // issue slot p+4 into ring slot (p+4)%RD
            int pn = p + 4;
            int slotn = pn % RD;
            #pragma unroll
            for (int kq = 0; kq < 2; kq++) {
                int k = kk * 2 + kq;
                int idx = SLOT * pn + k;
                if (idx > NS + 15) idx = NS + 15;
                int v = qsh[idx];
                int qq = v & 0xffff, rr2 = v >> 16;
                cp_async8(&ea_ring[(slotn * SLOT + k) * 128 + d2],
                          &g_ea[(qq * NK + rr2) * NDV + d2]);
            }
            if (tid < 52) {
                int idx = SLOT * pn + ka;
                if (idx > NS + 15) idx = NS + 15;
                int v = qsh[idx];
                int qq = v & 0xffff;
                cp_async16(&attn_ring[(slotn * SLOT + ka) * 56 + ia * 4],
                           g_attn + qq * 64 + ia * 4);
            }
            cp_commit();
        }

        BAR_SYNC(1, 256);            // final chunk's staging drained
        if (tid == 0) { __threadfence_block(); s_prod = NCH; }
        return;
    }

    // ---------------- CONSUMERS ----------------
    {
        int ct = tid - 256;          // 0..127
        __syncthreads();             // qsh + weights ready (all 384)

        int pg = ct / 13;
        int jg = ct - pg * 13;
        bool active = (ct < 104);
        int jbase = jg * 4;

        for (int c = 0; c < NCH; c++) {
            // wait for chunk c produced
            while (s_prod < c + 1) __nanosleep(200);
            __threadfence_block();

            float* rS = staging + (c & 1) * CH * SROW;  // [32][SROW]
            long  tp0 = (long)b * NS + (long)c * CH;    // global pos of chunk row 0

            ull acc[4][2];
            if (active) {
                #pragma unroll
                for (int pp = 0; pp < 4; pp++) { acc[pp][0] = 0ULL; acc[pp][1] = 0ULL; }
                for (int dd0 = 0; dd0 < 128; dd0 += 4) {
                    ulonglong2 wv[4];
                    #pragma unroll
                    for (int u = 0; u < 4; u++)
                        wv[u] = *(const ulonglong2*)&wS[(dd0 + u) * 52 + jbase];
                    #pragma unroll
                    for (int pp = 0; pp < 4; pp++) {
                        float4 rv = *(const float4*)&rS[(pg + pp * 8) * SROW + dd0];
                        ull r0 = pack2(rv.x, rv.x);
                        acc[pp][0] = ffma2(r0, wv[0].x, acc[pp][0]);
                        acc[pp][1] = ffma2(r0, wv[0].y, acc[pp][1]);
                        ull r1 = pack2(rv.y, rv.y);
                        acc[pp][0] = ffma2(r1, wv[1].x, acc[pp][0]);
                        acc[pp][1] = ffma2(r1, wv[1].y, acc[pp][1]);
                        ull r2 = pack2(rv.z, rv.z);
                        acc[pp][0] = ffma2(r2, wv[2].x, acc[pp][0]);
                        acc[pp][1] = ffma2(r2, wv[2].y, acc[pp][1]);
                        ull r3 = pack2(rv.w, rv.w);
                        acc[pp][0] = ffma2(r3, wv[3].x, acc[pp][0]);
                        acc[pp][1] = ffma2(r3, wv[3].y, acc[pp][1]);
                    }
                }
            }
            BAR_SYNC(2, 128);        // all rv reads done; reuse rS rows as sS

            float* sS = rS;          // 32 x 52 summary, overlapped
            if (active) {
                #pragma unroll
                for (int pp = 0; pp < 4; pp++) {
                    int pos = pg + pp * 8;
                    int q = qsh[c * CH + pos] & 0xffff;
                    float2 a01 = unpack2(acc[pp][0]);
                    float2 a23 = unpack2(acc[pp][1]);
                    float av[4] = {a01.x, a01.y, a23.x, a23.y};
                    #pragma unroll
                    for (int jj = 0; jj < 4; jj++) {
                        int j = jbase + jj;
                        float s = 0.f;
                        if (j < NDS)
                            s = tanhf(av[jj] + g_sumq[q * 64 + j] + sbS[j]);
                        sS[pos * 52 + j] = s;
                    }
                }
            }
            BAR_SYNC(2, 128);

            if (ct < CH) {
                long p = tp0 + ct;
                int q = qsh[c * CH + ct] & 0xffff;
                float th = theta_b[0];
                #pragma unroll
                for (int j = 0; j < NDS; j++) th = fmaf(sS[ct * 52 + j], twS[j], th);
                th = tanhf(th);
                float al = g_alpha[q];
                float inter = th * al;
                float bt[4];
                #pragma unroll
                for (int t = 0; t < 4; t++) bt[t] = g_beta[q * 4 + t];
                float lg[5];
                lg[0] = 0.f;
                float cc = 0.f;
                #pragma unroll
                for (int t = 0; t < 4; t++) { cc += inter - bt[t]; lg[t + 1] = cc; }
                float mx = lg[0];
                #pragma unroll
                for (int i = 1; i < 5; i++) mx = fmaxf(mx, lg[i]);
                float ex[5], den = 0.f;
                #pragma unroll
                for (int i = 0; i < 5; i++) { ex[i] = expf(lg[i] - mx); den += ex[i]; }
                float inv = 1.f / den;

                const long NBS = (long)NPOS;
                out[p]       = th;
                out[NBS + p] = al;
                #pragma unroll
                for (int t = 0; t < 4; t++) out[2 * NBS + p * 4 + t] = bt[t];
                #pragma unroll
                for (int i = 0; i < 5; i++) out[6 * NBS + p * 5 + i] = lg[i];
                #pragma unroll
                for (int i = 0; i < 5; i++) out[11 * NBS + p * 5 + i] = ex[i] * inv;
            }
            BAR_SYNC(2, 128);        // sS reads done before releasing chunk
            if (ct == 0) { __threadfence_block(); s_cons = c + 1; }
        }
    }
}

// ============================== launcher ==============================
extern "C" void kernel_launch(void* const* d_in, const int* in_sizes, int n_in,
                              void* d_out, int out_size) {
    const int*   questions    = (const int*)  d_in[0];
    const int*   responses    = (const int*)  d_in[1];
    const float* q_embed_w    = (const float*)d_in[2];
    const float* item_embed_w = (const float*)d_in[3];
    const float* value_proj_w = (const float*)d_in[4];
    const float* value_proj_b = (const float*)d_in[5];
    const float* key_mem      = (const float*)d_in[6];
    const float* init_mem     = (const float*)d_in[7];
    const float* erase_w      = (const float*)d_in[8];
    const float* erase_b      = (const float*)d_in[9];
    const float* add_w        = (const float*)d_in[10];
    const float* add_b        = (const float*)d_in[11];
    const float* summary_w    = (const float*)d_in[12];
    const float* summary_b    = (const float*)d_in[13];
    const float* theta_w      = (const float*)d_in[14];
    const float* theta_b      = (const float*)d_in[15];
    const float* alpha_w      = (const float*)d_in[16];
    const float* alpha_b      = (const float*)d_in[17];
    const float* beta_w       = (const float*)d_in[18];
    const float* beta_b       = (const float*)d_in[19];
    float* out = (float*)d_out;

    static int attr_set = 0;
    if (!attr_set) {
        cudaFuncSetAttribute(fused_scan_kernel,
                             cudaFuncAttributeMaxDynamicSharedMemorySize,
                             SMEM_TOTAL);
        attr_set = 1;
    }

    build_q_tables<<<NQ, 64>>>(q_embed_w, key_mem, summary_w,
                               alpha_w, alpha_b, beta_w, beta_b);
    build_qr_tables<<<NQ, 128>>>(item_embed_w, value_proj_w, value_proj_b,
                                 erase_w, erase_b, add_w, add_b);
    fused_scan_kernel<<<NB, 384, SMEM_TOTAL>>>(questions, responses, init_mem,
                                               summary_w, summary_b,
                                               theta_w, theta_b, out);
}

// round 15
// speedup vs baseline: 1.3822x; 1.0424x over previous
#include <cuda_runtime.h>
#include <cuda_bf16.h>
#include <math.h>

// Problem constants
#define NB   128
#define NS   2048
#define NM   50
#define NDK  64
#define NDV  128
#define NK   5
#define NDS  50
#define NQ   1001
#define NPOS (NB*NS)   // 262144

typedef unsigned long long ull;

// ---- packed f32x2 helpers (bit-identical per lane to scalar fp32) ----
__device__ __forceinline__ ull ffma2(ull a, ull b, ull c) {
    ull d;
    asm("fma.rn.f32x2 %0, %1, %2, %3;" : "=l"(d) : "l"(a), "l"(b), "l"(c));
    return d;
}
__device__ __forceinline__ ull fadd2(ull a, ull b) {
    ull d;
    asm("add.rn.f32x2 %0, %1, %2;" : "=l"(d) : "l"(a), "l"(b));
    return d;
}
__device__ __forceinline__ ull pack2(float lo, float hi) {
    ull r; asm("mov.b64 %0, {%1,%2};" : "=l"(r) : "f"(lo), "f"(hi)); return r;
}
__device__ __forceinline__ float2 unpack2(ull v) {
    float2 f; asm("mov.b64 {%0,%1}, %2;" : "=f"(f.x), "=f"(f.y) : "l"(v)); return f;
}

// ---- cp.async helpers ----
__device__ __forceinline__ void cp_async8(void* dst, const void* src) {
    unsigned s = (unsigned)__cvta_generic_to_shared(dst);
    asm volatile("cp.async.ca.shared.global [%0], [%1], 8;" :: "r"(s), "l"(src));
}
__device__ __forceinline__ void cp_async16(void* dst, const void* src) {
    unsigned s = (unsigned)__cvta_generic_to_shared(dst);
    asm volatile("cp.async.ca.shared.global [%0], [%1], 16;" :: "r"(s), "l"(src));
}
__device__ __forceinline__ void cp_commit() {
    asm volatile("cp.async.commit_group;");
}
__device__ __forceinline__ void cp_wait2() {
    asm volatile("cp.async.wait_group 2;");
}
#define BAR_SYNC(id, cnt) asm volatile("bar.sync %0, %1;" :: "r"(id), "r"(cnt) : "memory")

// -------- scratch (__device__ globals; no runtime allocation) --------
__device__ float  g_attn [NQ * 64];            // softmax(q_e @ key_mem^T); [50,64) ZERO
__device__ float  g_sumq [NQ * 64];            // q_e @ summary_w[128:192], stride 64
__device__ float  g_alpha[NQ];
__device__ float  g_beta [NQ * 4];
__device__ float2 g_ea   [NQ * NK * NDV];      // (.x=erase sigmoid, .y=add tanh)

// ======================= Phase A1: per-question tables =======================
__global__ void build_q_tables(const float* __restrict__ qe_w,
                               const float* __restrict__ key_mem,
                               const float* __restrict__ sum_w,
                               const float* __restrict__ alpha_w,
                               const float* __restrict__ alpha_b,
                               const float* __restrict__ beta_w,
                               const float* __restrict__ beta_b) {
    int q = blockIdx.x;
    int tid = threadIdx.x;           // 64 threads
    __shared__ float qe[64];
    __shared__ float lg[NM];
    qe[tid] = qe_w[q * 64 + tid];
    __syncthreads();

    if (tid < NM) {
        float a = 0.f, s = 0.f;
        #pragma unroll
        for (int k = 0; k < 64; k++) {
            float qk = qe[k];
            a = fmaf(qk, key_mem[tid * 64 + k], a);
            s = fmaf(qk, sum_w[(128 + k) * NDS + tid], s);
        }
        lg[tid] = a;
        g_sumq[q * 64 + tid] = s;
    }
    __syncthreads();

    if (tid < NM) {
        float mx = -1e30f;
        for (int m = 0; m < NM; m++) mx = fmaxf(mx, lg[m]);
        float den = 0.f;
        for (int m = 0; m < NM; m++) den += expf(lg[m] - mx);
        g_attn[q * 64 + tid] = expf(lg[tid] - mx) / den;
    } else {
        g_attn[q * 64 + tid] = 0.f;   // pad m in [50,64): weight 0 => inert
    }

    if (tid == 0) {
        float x = alpha_b[0];
        #pragma unroll
        for (int k = 0; k < 64; k++) x = fmaf(qe[k], alpha_w[k], x);
        g_alpha[q] = fmaxf(x, 0.f) + log1pf(expf(-fabsf(x)));
    }
    if (tid >= 1 && tid < 5) {
        int t = tid - 1;
        float x = beta_b[t];
        #pragma unroll
        for (int k = 0; k < 64; k++) x = fmaf(qe[k], beta_w[k * 4 + t], x);
        g_beta[q * 4 + t] = x;
    }
}

// ================= Phase A2: per-(question,response) erase/add =================
__global__ __launch_bounds__(128)
void build_qr_tables(const float* __restrict__ item_w,
                     const float* __restrict__ vp_w,
                     const float* __restrict__ vp_b,
                     const float* __restrict__ er_w,
                     const float* __restrict__ er_b,
                     const float* __restrict__ ad_w,
                     const float* __restrict__ ad_b) {
    int q = blockIdx.x;
    int v = threadIdx.x;             // 128 threads
    __shared__ float iv[64];
    __shared__ float veS[NK][NDV];

    if (v < 64) iv[v] = item_w[q * 64 + v];
    __syncthreads();

    float common = vp_b[v];
    #pragma unroll
    for (int i = 0; i < 64; i++) common = fmaf(iv[i], vp_w[i * NDV + v], common);
    #pragma unroll
    for (int r = 0; r < NK; r++) {
        float x = common;
        #pragma unroll
        for (int k = 0; k < NK; k++) {
            float rf = fmaxf(0.f, 1.f - fabsf((float)k - (float)r) * 0.25f);
            x = fmaf(rf, vp_w[(64 + k) * NDV + v], x);
        }
        veS[r][v] = x;
    }
    __syncthreads();

    int j = v;
    float eacc[NK], aacc[NK];
    #pragma unroll
    for (int r = 0; r < NK; r++) { eacc[r] = er_b[j]; aacc[r] = ad_b[j]; }
    for (int v2 = 0; v2 < NDV; v2++) {
        float we = er_w[v2 * NDV + j];
        float wa = ad_w[v2 * NDV + j];
        #pragma unroll
        for (int r = 0; r < NK; r++) {
            float t = veS[r][v2];
            eacc[r] = fmaf(t, we, eacc[r]);
            aacc[r] = fmaf(t, wa, aacc[r]);
        }
    }
    #pragma unroll
    for (int r = 0; r < NK; r++) {
        long base = ((long)q * NK + r) * NDV + j;
        g_ea[base] = make_float2(1.f / (1.f + expf(-eacc[r])), tanhf(aacc[r]));
    }
}

// ==================== Phase B (fused): scan + outputs ====================
// One CTA of 384 threads per batch element b.
//  Warps 0-7  (tid<256): PRODUCERS — cp.async-ring scan, slots of 8 steps,
//     ring RD=4, prefetch 3 slots (24 steps), bar.sync(1,256) once per slot.
//     attn is read from the ring directly as packed ull (no per-pair MOVs).
//  Warps 8-11 (tid>=256): CONSUMERS — per 32-step chunk: GEMM read@W + tanh
//     summary + theta/alpha/beta/logits/probs epilogue (bar.sync 2,128).
//  Producer->consumer: volatile s_prod counter + smem-bar drain.
//  Consumer->producer: volatile s_cons counter for staging reuse.
#define SLOT  8        // steps per ring slot / cp.async group
#define RD    4        // ring slots; prefetch depth 3
#define CH    32       // steps per staging chunk (= 4 slots)
#define NCH   (NS/CH)  // 64 chunks
#define SROW  132      // staging row stride (floats)

// dynamic smem layout (bytes)
#define OFF_QSH  0                          // (NS+16)*4            = 8256
#define OFF_EA   8256                       // RD*SLOT*128*8        = 32768
#define OFF_AT   41024                      // RD*SLOT*56*4         = 7168
#define OFF_STG  48192                      // 64*132*4             = 33792
#define OFF_WS   81984                      // 128*52*4             = 26624
#define OFF_TW   108608                     // 56*4                 = 224
#define OFF_SB   108832                     // 56*4                 = 224
#define SMEM_TOTAL 109056

__global__ __launch_bounds__(384, 1)
void fused_scan_kernel(const int* __restrict__ questions,
                       const int* __restrict__ responses,
                       const float* __restrict__ init_mem,
                       const float* __restrict__ sum_w,
                       const float* __restrict__ sum_b,
                       const float* __restrict__ theta_w,
                       const float* __restrict__ theta_b,
                       float* __restrict__ out) {
    extern __shared__ char smem[];
    int*    qsh       = (int*)   (smem + OFF_QSH);   // q | (r<<16)
    float2* ea_ring   = (float2*)(smem + OFF_EA);    // [RD][SLOT][128]
    float*  attn_ring = (float*) (smem + OFF_AT);    // [RD][SLOT][56]
    float*  staging   = (float*) (smem + OFF_STG);   // [64][SROW]
    float*  wS        = (float*) (smem + OFF_WS);    // [128][52]
    float*  twS       = (float*) (smem + OFF_TW);
    float*  sbS       = (float*) (smem + OFF_SB);

    __shared__ volatile int s_prod;   // chunks produced
    __shared__ volatile int s_cons;   // chunks consumed

    int b   = blockIdx.x;
    int tid = threadIdx.x;

    if (tid == 0) { s_prod = 0; s_cons = 0; }

    if (tid < 256) {
        // producers load qsh
        for (int i = tid; i < NS; i += 256)
            qsh[i] = questions[b * NS + i] | (responses[b * NS + i] << 16);
    } else {
        // consumers load weight tiles
        int ct = tid - 256;          // 0..127
        for (int i = ct; i < 128 * 52; i += 128) {
            int dd = i / 52, j = i % 52;
            wS[i] = (j < NDS) ? sum_w[dd * NDS + j] : 0.f;
        }
        if (ct < 52) {
            twS[ct] = (ct < NDS) ? theta_w[ct] : 0.f;
            sbS[ct] = (ct < NDS) ? sum_b[ct] : 0.f;
        }
    }

    // ---------------- PRODUCERS ----------------
    if (tid < 256) {
        int part = tid & 1;
        int d = tid >> 1;            // 0..127

        // cp duty assignment for a slot of 8 steps:
        //  ea:   tid<128 -> steps 0..3, tid>=128 -> steps 4..7 (4 cp8 each, col d2)
        //  attn: tid<104 -> one cp16: step ka = tid/13, 16B chunk ia = tid%13
        int d2 = tid & 127;
        int sk = (tid >> 7) * 4;     // starting step of this thread's ea duty
        int ka = (tid < 104) ? (tid / 13) : 0;
        int ia = (tid < 104) ? (tid % 13) : 0;

        // init mem: part p owns pairs [13p,13p+13); pair pi covers m=2pi,2pi+1
        ull mem2[13];
        #pragma unroll
        for (int jj = 0; jj < 13; jj++) {
            int pi = 13 * part + jj;
            float lo = (2 * pi < NM)     ? init_mem[(2 * pi) * NDV + d]     : 0.f;
            float hi = (2 * pi + 1 < NM) ? init_mem[(2 * pi + 1) * NDV + d] : 0.f;
            mem2[jj] = pack2(lo, hi);
        }
        __syncthreads();             // qsh + weights ready (all 384)

        // prologue: issue slots 0..2 (steps 0..23)
        #pragma unroll
        for (int p = 0; p < 3; p++) {
            #pragma unroll
            for (int i = 0; i < 4; i++) {
                int k = sk + i;
                int v = qsh[SLOT * p + k];
                int qq = v & 0xffff, rr = v >> 16;
                cp_async8(&ea_ring[(p * SLOT + k) * 128 + d2],
                          &g_ea[(qq * NK + rr) * NDV + d2]);
            }
            if (tid < 104) {
                int v = qsh[SLOT * p + ka];
                int qq = v & 0xffff;
                cp_async16(&attn_ring[(p * SLOT + ka) * 56 + ia * 4],
                           g_attn + qq * 64 + ia * 4);
            }
            cp_commit();
        }

        float* outstg = staging;

        for (int p = 0; p < NS / SLOT; p++) {
            cp_wait2();              // slot p complete
            BAR_SYNC(1, 256);        // ring slot + prior staging stores visible

            // chunk bookkeeping every CH/SLOT = 4 slots
            if ((p & 3) == 0) {
                int c = p >> 2;
                if (c > 0 && tid == 0) { __threadfence_block(); s_prod = c; }
                if (c >= 2) {
                    while (s_cons < c - 1) __nanosleep(200);
                }
            }

            int slot = p % RD;
            #pragma unroll
            for (int k = 0; k < SLOT; k++) {
                int t = SLOT * p + k;
                float2 ea = ea_ring[(slot * SLOT + k) * 128 + d];
                ull ne2 = pack2(-ea.x, -ea.x);
                ull a2  = pack2(ea.y, ea.y);
                const ull* at =
                    (const ull*)(attn_ring + (slot * SLOT + k) * 56) + 13 * part;

                ull r0 = 0ULL, r1 = 0ULL;
                #pragma unroll
                for (int jj = 0; jj < 13; jj++) {
                    ull w2 = at[jj];
                    ull mo = mem2[jj];
                    if (jj & 1) r1 = ffma2(w2, mo, r1);
                    else        r0 = ffma2(w2, mo, r0);
                    mem2[jj] = ffma2(w2, ffma2(mo, ne2, a2), mo);
                }
                float2 rr = unpack2(fadd2(r0, r1));
                float rsum = rr.x + rr.y;
                rsum += __shfl_xor_sync(0xffffffffu, rsum, 1);
                if (part == 0) outstg[(t & 63) * SROW + d] = rsum;
            }

            // issue slot p+3 into ring slot (p+3)%RD
            int pn = p + 3;
            int slotn = pn % RD;
            #pragma unroll
            for (int i = 0; i < 4; i++) {
                int k = sk + i;
                int idx = SLOT * pn + k;
                if (idx > NS - 1) idx = NS - 1;
                int v = qsh[idx];
                int qq = v & 0xffff, rr2 = v >> 16;
                cp_async8(&ea_ring[(slotn * SLOT + k) * 128 + d2],
                          &g_ea[(qq * NK + rr2) * NDV + d2]);
            }
            if (tid < 104) {
                int idx = SLOT * pn + ka;
                if (idx > NS - 1) idx = NS - 1;
                int v = qsh[idx];
                int qq = v & 0xffff;
                cp_async16(&attn_ring[(slotn * SLOT + ka) * 56 + ia * 4],
                           g_attn + qq * 64 + ia * 4);
            }
            cp_commit();             // keep group count in sync
        }

        BAR_SYNC(1, 256);            // final chunk's staging drained
        if (tid == 0) { __threadfence_block(); s_prod = NCH; }
        return;
    }

    // ---------------- CONSUMERS ----------------
    {
        int ct = tid - 256;          // 0..127
        __syncthreads();             // qsh + weights ready (all 384)

        int pg = ct / 13;
        int jg = ct - pg * 13;
        bool active = (ct < 104);
        int jbase = jg * 4;

        for (int c = 0; c < NCH; c++) {
            // wait for chunk c produced
            while (s_prod < c + 1) __nanosleep(200);
            __threadfence_block();

            float* rS = staging + (c & 1) * CH * SROW;  // [32][SROW]
            long  tp0 = (long)b * NS + (long)c * CH;    // global pos of chunk row 0

            ull acc[4][2];
            if (active) {
                #pragma unroll
                for (int pp = 0; pp < 4; pp++) { acc[pp][0] = 0ULL; acc[pp][1] = 0ULL; }
                for (int dd0 = 0; dd0 < 128; dd0 += 4) {
                    ulonglong2 wv[4];
                    #pragma unroll
                    for (int u = 0; u < 4; u++)
                        wv[u] = *(const ulonglong2*)&wS[(dd0 + u) * 52 + jbase];
                    #pragma unroll
                    for (int pp = 0; pp < 4; pp++) {
                        float4 rv = *(const float4*)&rS[(pg + pp * 8) * SROW + dd0];
                        ull r0 = pack2(rv.x, rv.x);
                        acc[pp][0] = ffma2(r0, wv[0].x, acc[pp][0]);
                        acc[pp][1] = ffma2(r0, wv[0].y, acc[pp][1]);
                        ull r1 = pack2(rv.y, rv.y);
                        acc[pp][0] = ffma2(r1, wv[1].x, acc[pp][0]);
                        acc[pp][1] = ffma2(r1, wv[1].y, acc[pp][1]);
                        ull r2 = pack2(rv.z, rv.z);
                        acc[pp][0] = ffma2(r2, wv[2].x, acc[pp][0]);
                        acc[pp][1] = ffma2(r2, wv[2].y, acc[pp][1]);
                        ull r3 = pack2(rv.w, rv.w);
                        acc[pp][0] = ffma2(r3, wv[3].x, acc[pp][0]);
                        acc[pp][1] = ffma2(r3, wv[3].y, acc[pp][1]);
                    }
                }
            }
            BAR_SYNC(2, 128);        // all rv reads done; reuse rS rows as sS

            float* sS = rS;          // 32 x 52 summary, overlapped
            if (active) {
                #pragma unroll
                for (int pp = 0; pp < 4; pp++) {
                    int pos = pg + pp * 8;
                    int q = qsh[c * CH + pos] & 0xffff;
                    float2 a01 = unpack2(acc[pp][0]);
                    float2 a23 = unpack2(acc[pp][1]);
                    float av[4] = {a01.x, a01.y, a23.x, a23.y};
                    #pragma unroll
                    for (int jj = 0; jj < 4; jj++) {
                        int j = jbase + jj;
                        float s = 0.f;
                        if (j < NDS)
                            s = tanhf(av[jj] + g_sumq[q * 64 + j] + sbS[j]);
                        sS[pos * 52 + j] = s;
                    }
                }
            }
            BAR_SYNC(2, 128);

            if (ct < CH) {
                long p = tp0 + ct;
                int q = qsh[c * CH + ct] & 0xffff;
                float th = theta_b[0];
                #pragma unroll
                for (int j = 0; j < NDS; j++) th = fmaf(sS[ct * 52 + j], twS[j], th);
                th = tanhf(th);
                float al = g_alpha[q];
                float inter = th * al;
                float bt[4];
                #pragma unroll
                for (int t = 0; t < 4; t++) bt[t] = g_beta[q * 4 + t];
                float lg[5];
                lg[0] = 0.f;
                float cc = 0.f;
                #pragma unroll
                for (int t = 0; t < 4; t++) { cc += inter - bt[t]; lg[t + 1] = cc; }
                float mx = lg[0];
                #pragma unroll
                for (int i = 1; i < 5; i++) mx = fmaxf(mx, lg[i]);
                float ex[5], den = 0.f;
                #pragma unroll
                for (int i = 0; i < 5; i++) { ex[i] = expf(lg[i] - mx); den += ex[i]; }
                float inv = 1.f / den;

                const long NBS = (long)NPOS;
                out[p]       = th;
                out[NBS + p] = al;
                #pragma unroll
                for (int t = 0; t < 4; t++) out[2 * NBS + p * 4 + t] = bt[t];
                #pragma unroll
                for (int i = 0; i < 5; i++) out[6 * NBS + p * 5 + i] = lg[i];
                #pragma unroll
                for (int i = 0; i < 5; i++) out[11 * NBS + p * 5 + i] = ex[i] * inv;
            }
            BAR_SYNC(2, 128);        // sS reads done before releasing chunk
            if (ct == 0) { __threadfence_block(); s_cons = c + 1; }
        }
    }
}

// ============================== launcher ==============================
extern "C" void kernel_launch(void* const* d_in, const int* in_sizes, int n_in,
                              void* d_out, int out_size) {
    const int*   questions    = (const int*)  d_in[0];
    const int*   responses    = (const int*)  d_in[1];
    const float* q_embed_w    = (const float*)d_in[2];
    const float* item_embed_w = (const float*)d_in[3];
    const float* value_proj_w = (const float*)d_in[4];
    const float* value_proj_b = (const float*)d_in[5];
    const float* key_mem      = (const float*)d_in[6];
    const float* init_mem     = (const float*)d_in[7];
    const float* erase_w      = (const float*)d_in[8];
    const float* erase_b      = (const float*)d_in[9];
    const float* add_w        = (const float*)d_in[10];
    const float* add_b        = (const float*)d_in[11];
    const float* summary_w    = (const float*)d_in[12];
    const float* summary_b    = (const float*)d_in[13];
    const float* theta_w      = (const float*)d_in[14];
    const float* theta_b      = (const float*)d_in[15];
    const float* alpha_w      = (const float*)d_in[16];
    const float* alpha_b      = (const float*)d_in[17];
    const float* beta_w       = (const float*)d_in[18];
    const float* beta_b       = (const float*)d_in[19];
    float* out = (float*)d_out;

    static int attr_set = 0;
    if (!attr_set) {
        cudaFuncSetAttribute(fused_scan_kernel,
                             cudaFuncAttributeMaxDynamicSharedMemorySize,
                             SMEM_TOTAL);
        attr_set = 1;
    }

    build_q_tables<<<NQ, 64>>>(q_embed_w, key_mem, summary_w,
                               alpha_w, alpha_b, beta_w, beta_b);
    build_qr_tables<<<NQ, 128>>>(item_embed_w, value_proj_w, value_proj_b,
                                 erase_w, erase_b, add_w, add_b);
    fused_scan_kernel<<<NB, 384, SMEM_TOTAL>>>(questions, responses, init_mem,
                                               summary_w, summary_b,
                                               theta_w, theta_b, out);
}